// round 6
// baseline (speedup 1.0000x reference)
#include <cuda_runtime.h>
#include <cuda_bf16.h>
#include <math.h>

// ---------------------------------------------------------------------------
// DilatedAttention: B=4, L=8192, D=768, SEG=2048, RATE=4  ->  Ls=2048/batch
//   1. gather every 4th row within each 2048-segment      (fused into proj)
//   2. q,k,v = x @ W^T                                     (3x GEMM 8192x768x768)
//   3. LayerNorm(q), LayerNorm(k)
//   4. S = q k^T / sqrt(768); P = softmax_rows(S)          (4x GEMM 2048x2048x768)
//   5. O = P v                                             (4x GEMM 2048x768x2048)
//   6. out = softmax_features(O)
// ---------------------------------------------------------------------------

#define B_      4
#define L_      8192
#define D_      768
#define LS_     2048            // sparse rows per batch
#define MTOT    (B_ * LS_)      // 8192

// scratch (allocation-free rule: __device__ globals)
__device__ float g_q[(long)MTOT * D_];
__device__ float g_k[(long)MTOT * D_];
__device__ float g_v[(long)MTOT * D_];
__device__ float g_s[(long)B_ * LS_ * LS_];   // 64 MB score matrix
__device__ float g_o[(long)MTOT * D_];

// ---------------------------------------------------------------------------
// SGEMM: 128x128 blocktile, BK=16, 8x8 threadtile, 256 threads.
//   GATHER:  A rows remapped through the dilation index (proj stage only)
//   B_IS_NK: B stored [N,K] (C = A B^T) vs [K,N] (C = A B)
// ---------------------------------------------------------------------------
#define BM 128
#define BN 128
#define BK 16
#define TM 8
#define TN 8

template<bool GATHER, bool B_IS_NK>
__global__ void __launch_bounds__(256)
sgemm_kernel(const float* __restrict__ A, const float* __restrict__ Bm,
             float* __restrict__ C, int M, int N, int K, float alpha,
             long sAb, long sBb, long sCb)
{
    const int b = blockIdx.z;
    A  += (long)b * sAb;
    Bm += (long)b * sBb;
    C  += (long)b * sCb;

    __shared__ __align__(16) float As[BK][BM];
    __shared__ __align__(16) float Bs[BK][BN];

    const int tid  = threadIdx.x;
    const int bm0  = blockIdx.y * BM;
    const int bn0  = blockIdx.x * BN;
    const int tcol = tid & 15;   // along N
    const int trow = tid >> 4;   // along M

    float acc[TM][TN] = {};

    for (int k0 = 0; k0 < K; k0 += BK) {
        // ---- load A tile (128 rows x 16 k), stored transposed As[k][m] ----
        #pragma unroll
        for (int i = 0; i < 2; i++) {
            int f   = tid + i * 256;            // 0..511 float4 slots
            int row = f >> 2;                    // 0..127
            int c4  = (f & 3) << 2;              // 0,4,8,12
            int gm  = bm0 + row;
            long srcRow;
            if (GATHER) {
                int b2 = gm >> 11;               // batch (2048 rows each)
                int s  = gm & 2047;
                srcRow = (long)b2 * L_ + ((s >> 9) << 11) + ((s & 511) << 2);
            } else {
                srcRow = gm;
            }
            float4 v = *(const float4*)(A + srcRow * K + k0 + c4);
            As[c4 + 0][row] = v.x;
            As[c4 + 1][row] = v.y;
            As[c4 + 2][row] = v.z;
            As[c4 + 3][row] = v.w;
        }
        // ---- load B tile ----
        if (B_IS_NK) {
            #pragma unroll
            for (int i = 0; i < 2; i++) {
                int f   = tid + i * 256;
                int row = f >> 2;                // n in 0..127
                int c4  = (f & 3) << 2;          // k
                float4 v = *(const float4*)(Bm + (long)(bn0 + row) * K + k0 + c4);
                Bs[c4 + 0][row] = v.x;
                Bs[c4 + 1][row] = v.y;
                Bs[c4 + 2][row] = v.z;
                Bs[c4 + 3][row] = v.w;
            }
        } else {
            #pragma unroll
            for (int i = 0; i < 2; i++) {
                int f    = tid + i * 256;
                int krow = f >> 5;               // 0..15
                int c4   = (f & 31) << 2;        // n offset 0..124
                float4 v = *(const float4*)(Bm + (long)(k0 + krow) * N + bn0 + c4);
                *(float4*)&Bs[krow][c4] = v;
            }
        }
        __syncthreads();

        // ---- compute ----
        #pragma unroll
        for (int kk = 0; kk < BK; kk++) {
            float4 a0 = *(const float4*)&As[kk][trow * TM];
            float4 a1 = *(const float4*)&As[kk][trow * TM + 4];
            float4 b0 = *(const float4*)&Bs[kk][tcol * TN];
            float4 b1 = *(const float4*)&Bs[kk][tcol * TN + 4];
            float aR[TM] = {a0.x, a0.y, a0.z, a0.w, a1.x, a1.y, a1.z, a1.w};
            float bR[TN] = {b0.x, b0.y, b0.z, b0.w, b1.x, b1.y, b1.z, b1.w};
            #pragma unroll
            for (int i = 0; i < TM; i++)
                #pragma unroll
                for (int j = 0; j < TN; j++)
                    acc[i][j] += aR[i] * bR[j];
        }
        __syncthreads();
    }

    // ---- epilogue ----
    #pragma unroll
    for (int i = 0; i < TM; i++) {
        long gm = bm0 + trow * TM + i;
        #pragma unroll
        for (int j = 0; j < TN; j += 4) {
            float4 v;
            v.x = acc[i][j + 0] * alpha;
            v.y = acc[i][j + 1] * alpha;
            v.z = acc[i][j + 2] * alpha;
            v.w = acc[i][j + 3] * alpha;
            *(float4*)(C + gm * N + bn0 + tcol * TN + j) = v;
        }
    }
}

// ---------------------------------------------------------------------------
// block reductions (256 threads)
// ---------------------------------------------------------------------------
__device__ __forceinline__ float block_sum(float v) {
    __shared__ float sh[8];
    int lane = threadIdx.x & 31, w = threadIdx.x >> 5;
    #pragma unroll
    for (int o = 16; o > 0; o >>= 1) v += __shfl_xor_sync(0xffffffffu, v, o);
    __syncthreads();
    if (lane == 0) sh[w] = v;
    __syncthreads();
    float t = 0.f;
    #pragma unroll
    for (int i = 0; i < 8; i++) t += sh[i];
    return t;
}

__device__ __forceinline__ float block_max(float v) {
    __shared__ float sh[8];
    int lane = threadIdx.x & 31, w = threadIdx.x >> 5;
    #pragma unroll
    for (int o = 16; o > 0; o >>= 1) v = fmaxf(v, __shfl_xor_sync(0xffffffffu, v, o));
    __syncthreads();
    if (lane == 0) sh[w] = v;
    __syncthreads();
    float t = -3.4e38f;
    #pragma unroll
    for (int i = 0; i < 8; i++) t = fmaxf(t, sh[i]);
    return t;
}

// ---------------------------------------------------------------------------
// LayerNorm (in place), one block per row, D=768
// ---------------------------------------------------------------------------
__global__ void __launch_bounds__(256)
ln_kernel(float* __restrict__ x, const float* __restrict__ gamma,
          const float* __restrict__ beta)
{
    float* p = x + (long)blockIdx.x * D_;
    int t = threadIdx.x;
    float v0 = p[t], v1 = p[t + 256], v2 = p[t + 512];
    float mean = block_sum(v0 + v1 + v2) * (1.0f / D_);
    float d0 = v0 - mean, d1 = v1 - mean, d2 = v2 - mean;
    float var = block_sum(d0 * d0 + d1 * d1 + d2 * d2) * (1.0f / D_);
    float rstd = rsqrtf(var + 1e-5f);
    p[t]       = d0 * rstd * gamma[t]       + beta[t];
    p[t + 256] = d1 * rstd * gamma[t + 256] + beta[t + 256];
    p[t + 512] = d2 * rstd * gamma[t + 512] + beta[t + 512];
}

// ---------------------------------------------------------------------------
// softmax over 2048 cols, in place, one block per row
// ---------------------------------------------------------------------------
__global__ void __launch_bounds__(256)
softmax2048_kernel(float* __restrict__ S)
{
    float* p = S + (long)blockIdx.x * LS_;
    int t = threadIdx.x;
    float v[8];
    float m = -3.4e38f;
    #pragma unroll
    for (int i = 0; i < 8; i++) { v[i] = p[t + i * 256]; m = fmaxf(m, v[i]); }
    m = block_max(m);
    float s = 0.f;
    #pragma unroll
    for (int i = 0; i < 8; i++) { v[i] = __expf(v[i] - m); s += v[i]; }
    s = block_sum(s);
    float inv = 1.0f / s;
    #pragma unroll
    for (int i = 0; i < 8; i++) p[t + i * 256] = v[i] * inv;
}

// ---------------------------------------------------------------------------
// final softmax over D=768, writes d_out
// ---------------------------------------------------------------------------
__global__ void __launch_bounds__(256)
softmax768_kernel(const float* __restrict__ O, float* __restrict__ out)
{
    const float* p = O  + (long)blockIdx.x * D_;
    float*       q = out + (long)blockIdx.x * D_;
    int t = threadIdx.x;
    float v0 = p[t], v1 = p[t + 256], v2 = p[t + 512];
    float m = block_max(fmaxf(v0, fmaxf(v1, v2)));
    v0 = __expf(v0 - m); v1 = __expf(v1 - m); v2 = __expf(v2 - m);
    float inv = 1.0f / block_sum(v0 + v1 + v2);
    q[t] = v0 * inv; q[t + 256] = v1 * inv; q[t + 512] = v2 * inv;
}

// ---------------------------------------------------------------------------
extern "C" void kernel_launch(void* const* d_in, const int* in_sizes, int n_in,
                              void* d_out, int out_size)
{
    const float* Q     = (const float*)d_in[0];
    const float* K     = (const float*)d_in[1];
    const float* V     = (const float*)d_in[2];
    const float* Wq    = (const float*)d_in[3];
    const float* Wk    = (const float*)d_in[4];
    const float* Wv    = (const float*)d_in[5];
    const float* gamma = (const float*)d_in[6];
    const float* beta  = (const float*)d_in[7];
    float* out = (float*)d_out;

    float *gq, *gk, *gv, *gs, *go;
    cudaGetSymbolAddress((void**)&gq, g_q);
    cudaGetSymbolAddress((void**)&gk, g_k);
    cudaGetSymbolAddress((void**)&gv, g_v);
    cudaGetSymbolAddress((void**)&gs, g_s);
    cudaGetSymbolAddress((void**)&go, g_o);

    const dim3 blk(256);
    const float scale = 1.0f / sqrtf((float)D_);

    // 1. gather + projections:  C[8192,768] = gather(X) @ W^T
    sgemm_kernel<true, true><<<dim3(D_ / BN, MTOT / BM, 1), blk>>>(
        Q, Wq, gq, MTOT, D_, D_, 1.0f, 0, 0, 0);
    sgemm_kernel<true, true><<<dim3(D_ / BN, MTOT / BM, 1), blk>>>(
        K, Wk, gk, MTOT, D_, D_, 1.0f, 0, 0, 0);
    sgemm_kernel<true, true><<<dim3(D_ / BN, MTOT / BM, 1), blk>>>(
        V, Wv, gv, MTOT, D_, D_, 1.0f, 0, 0, 0);

    // 2. qk LayerNorm
    ln_kernel<<<MTOT, blk>>>(gq, gamma, beta);
    ln_kernel<<<MTOT, blk>>>(gk, gamma, beta);

    // 3. S = q k^T * scale   (per batch, NT)
    sgemm_kernel<false, true><<<dim3(LS_ / BN, LS_ / BM, B_), blk>>>(
        gq, gk, gs, LS_, LS_, D_, scale,
        (long)LS_ * D_, (long)LS_ * D_, (long)LS_ * LS_);

    // 4. row softmax
    softmax2048_kernel<<<B_ * LS_, blk>>>(gs);

    // 5. O = P v   (per batch, NN)
    sgemm_kernel<false, false><<<dim3(D_ / BN, LS_ / BM, B_), blk>>>(
        gs, gv, go, LS_, D_, LS_, 1.0f,
        (long)LS_ * LS_, (long)LS_ * D_, (long)LS_ * D_);

    // 6. feature softmax -> out
    softmax768_kernel<<<MTOT, blk>>>(go, out);
}

// round 8
// speedup vs baseline: 2.9874x; 2.9874x over previous
#include <cuda_runtime.h>
#include <cuda_bf16.h>
#include <math.h>
#include <stdint.h>

// ---------------------------------------------------------------------------
// DilatedAttention via mma.sync bf16 (3-pass error-compensated split).
// tcgen05 is unavailable: harness ptxas targets plain sm_103 (no 'a' suffix),
// which rejects all tcgen05/TMEM instructions. mma.sync+ldmatrix are base PTX.
//   B=4, L=8192, D=768, SEG=2048, RATE=4 -> Ls=2048/batch, MTOT=8192
// ---------------------------------------------------------------------------

#define B_      4
#define L_      8192
#define D_      768
#define LS_     2048
#define MTOT    (B_ * LS_)

__device__ float g_q[(long)MTOT * D_];
__device__ float g_k[(long)MTOT * D_];
__device__ float g_vT[(long)B_ * D_ * LS_];    // projected V, transposed per batch
__device__ float g_s[(long)B_ * LS_ * LS_];    // 64 MB scores
__device__ float g_o[(long)MTOT * D_];

// ---------------- smem geometry -------------------------------------------
#define BM    128
#define BN    128
#define BKF   32                      // K per tile (elements)
#define ROWB  80                      // 64B data + 16B pad per row
#define PLANE (128 * ROWB)            // 10240 B
#define STAGE (4 * PLANE)             // Ah, Al, Bh, Bl  = 40960 B
#define SMEMSZ (2 * STAGE)            // double buffered  = 81920 B

__device__ __forceinline__ uint32_t smem_u32(const void* p) {
    uint32_t a;
    asm("{ .reg .u64 t; cvta.to.shared.u64 t, %1; cvt.u32.u64 %0, t; }" : "=r"(a) : "l"(p));
    return a;
}

#define LDSM4(r, addr) \
    asm volatile("ldmatrix.sync.aligned.m8n8.x4.shared.b16 {%0,%1,%2,%3}, [%4];" \
        : "=r"((r)[0]), "=r"((r)[1]), "=r"((r)[2]), "=r"((r)[3]) : "r"(addr))

#define MMA_BF16(d, a, b) \
    asm volatile("mma.sync.aligned.m16n8k16.row.col.f32.bf16.bf16.f32 " \
        "{%0,%1,%2,%3}, {%4,%5,%6,%7}, {%8,%9}, {%0,%1,%2,%3};" \
        : "+f"((d)[0]), "+f"((d)[1]), "+f"((d)[2]), "+f"((d)[3]) \
        : "r"((a)[0]), "r"((a)[1]), "r"((a)[2]), "r"((a)[3]), "r"((b)[0]), "r"((b)[1]))

// ---------------- gmem -> regs (fp32), 4 float4 per thread -----------------
template<bool GATHER>
__device__ __forceinline__ void ldg_tile(const float* __restrict__ src, int ld,
                                         int rowBase, int k0, int tid, float4* reg)
{
    #pragma unroll
    for (int i = 0; i < 4; i++) {
        int f = tid + (i << 8);          // 0..1023 float4 slots (128 rows x 8)
        int r = f >> 3;
        int c = (f & 7) << 2;
        int gm = rowBase + r;
        long sr;
        if (GATHER) {
            int s = gm & 2047;
            sr = (long)(gm >> 11) * L_ + ((s >> 9) << 11) + ((s & 511) << 2);
        } else {
            sr = gm;
        }
        reg[i] = *(const float4*)(src + sr * (long)ld + k0 + c);
    }
}

// ---------------- regs -> smem hi/lo planes --------------------------------
__device__ __forceinline__ void sts_tile(const float4* reg, char* hiP, char* loP, int tid)
{
    #pragma unroll
    for (int i = 0; i < 4; i++) {
        float4 v = reg[i];
        int f = tid + (i << 8);
        int r = f >> 3;
        int c = (f & 7) << 2;
        __nv_bfloat162 h01 = __floats2bfloat162_rn(v.x, v.y);
        __nv_bfloat162 h23 = __floats2bfloat162_rn(v.z, v.w);
        float lx = v.x - __bfloat162float(h01.x);
        float ly = v.y - __bfloat162float(h01.y);
        float lz = v.z - __bfloat162float(h23.x);
        float lw = v.w - __bfloat162float(h23.y);
        __nv_bfloat162 l01 = __floats2bfloat162_rn(lx, ly);
        __nv_bfloat162 l23 = __floats2bfloat162_rn(lz, lw);
        uint32_t off = (uint32_t)(r * ROWB + (c << 1));
        uint2 hv, lv;
        hv.x = *(uint32_t*)&h01; hv.y = *(uint32_t*)&h23;
        lv.x = *(uint32_t*)&l01; lv.y = *(uint32_t*)&l23;
        *(uint2*)(hiP + off) = hv;
        *(uint2*)(loP + off) = lv;
    }
}

// ---------------- GEMM: C[128x128] = A[128xK] * B[128xK]^T -----------------
// GATHER: dilation remap on A rows.  OUTMODE: 0 row-major C, 1 vT transposed.
template<bool GATHER, int OUTMODE>
__global__ void __launch_bounds__(256)
tc_gemm(const float* __restrict__ A, const float* __restrict__ Bm,
        float* __restrict__ C, int K, float alpha,
        long sAb, long sBb, long sCb, int ldA, int ldB, int ldC)
{
    extern __shared__ char sm[];
    const uint32_t smem_base = smem_u32(sm);
    const int tid  = threadIdx.x;
    const int wid  = tid >> 5;
    const int lane = tid & 31;
    const int warpM = wid & 3;        // 4 along M
    const int warpN = wid >> 2;       // 2 along N
    const int bz = blockIdx.z;

    A  += (long)bz * sAb;
    Bm += (long)bz * sBb;
    C  += (long)bz * sCb;

    const int bm0 = blockIdx.y * BM;
    const int bn0 = blockIdx.x * BN;

    float acc[2][8][4] = {};
    float4 ra[4], rb[4];

    const int NC = K / BKF;

    // prologue: fill buffer 0
    ldg_tile<GATHER>(A,  ldA, bm0, 0, tid, ra);
    ldg_tile<false >(Bm, ldB, bn0, 0, tid, rb);
    sts_tile(ra, sm, sm + PLANE, tid);
    sts_tile(rb, sm + 2 * PLANE, sm + 3 * PLANE, tid);
    __syncthreads();

    // ldmatrix lane addressing (constant across iterations, varies with k16)
    const int aRow = warpM * 32 + (lane & 15);                     // + mt*16
    const int aKof = (lane >> 4) << 3;
    const int bRow = warpN * 64 + ((lane >> 4) << 3) + (lane & 7); // + np*16
    const int bKof = ((lane >> 3) & 1) << 3;

    for (int c = 0; c < NC; c++) {
        const int buf = c & 1;
        if (c + 1 < NC) {
            ldg_tile<GATHER>(A,  ldA, bm0, (c + 1) * BKF, tid, ra);
            ldg_tile<false >(Bm, ldB, bn0, (c + 1) * BKF, tid, rb);
        }

        const uint32_t sb  = smem_base + buf * STAGE;
        const uint32_t aHi = sb, aLo = sb + PLANE;
        const uint32_t bHi = sb + 2 * PLANE, bLo = sb + 3 * PLANE;

        #pragma unroll
        for (int k16 = 0; k16 < 2; k16++) {
            const int kk = k16 << 4;
            uint32_t ah[2][4], al[2][4], bh[8][2], bl[8][2];
            #pragma unroll
            for (int mt = 0; mt < 2; mt++) {
                uint32_t off = (uint32_t)((aRow + mt * 16) * ROWB + (kk + aKof) * 2);
                LDSM4(ah[mt], aHi + off);
                LDSM4(al[mt], aLo + off);
            }
            #pragma unroll
            for (int np = 0; np < 4; np++) {
                uint32_t off = (uint32_t)((bRow + np * 16) * ROWB + (kk + bKof) * 2);
                uint32_t r[4];
                LDSM4(r, bHi + off);
                bh[np*2][0] = r[0]; bh[np*2][1] = r[1];
                bh[np*2+1][0] = r[2]; bh[np*2+1][1] = r[3];
                LDSM4(r, bLo + off);
                bl[np*2][0] = r[0]; bl[np*2][1] = r[1];
                bl[np*2+1][0] = r[2]; bl[np*2+1][1] = r[3];
            }
            #pragma unroll
            for (int mt = 0; mt < 2; mt++)
                #pragma unroll
                for (int nt = 0; nt < 8; nt++) {
                    MMA_BF16(acc[mt][nt], ah[mt], bh[nt]);
                    MMA_BF16(acc[mt][nt], ah[mt], bl[nt]);
                    MMA_BF16(acc[mt][nt], al[mt], bh[nt]);
                }
        }

        if (c + 1 < NC) {
            char* nb = sm + (buf ^ 1) * STAGE;
            sts_tile(ra, nb, nb + PLANE, tid);
            sts_tile(rb, nb + 2 * PLANE, nb + 3 * PLANE, tid);
        }
        __syncthreads();
    }

    // ---------------- epilogue ----------------
    const int groupID = lane >> 2, tig = lane & 3;
    #pragma unroll
    for (int mt = 0; mt < 2; mt++)
        #pragma unroll
        for (int nt = 0; nt < 8; nt++) {
            float* a = acc[mt][nt];
            const int row = bm0 + warpM * 32 + mt * 16 + groupID;
            const int col = bn0 + warpN * 64 + nt * 8 + tig * 2;
            if (OUTMODE == 0) {
                *(float2*)(C + (long)row * ldC + col) =
                    make_float2(a[0] * alpha, a[1] * alpha);
                *(float2*)(C + (long)(row + 8) * ldC + col) =
                    make_float2(a[2] * alpha, a[3] * alpha);
            } else {
                const int b2 = row >> 11, tok = row & 2047;
                float* cp = C + (long)b2 * D_ * LS_ + tok;
                cp[(long)col * LS_]           = a[0] * alpha;
                cp[(long)(col + 1) * LS_]     = a[1] * alpha;
                cp[(long)col * LS_ + 8]       = a[2] * alpha;
                cp[(long)(col + 1) * LS_ + 8] = a[3] * alpha;
            }
        }
}

// ======================= reductions / pointwise ============================
__device__ __forceinline__ float block_sum(float v) {
    __shared__ float sh[8];
    int lane = threadIdx.x & 31, w = threadIdx.x >> 5;
    #pragma unroll
    for (int o = 16; o > 0; o >>= 1) v += __shfl_xor_sync(0xffffffffu, v, o);
    __syncthreads();
    if (lane == 0) sh[w] = v;
    __syncthreads();
    float t = 0.f;
    #pragma unroll
    for (int i = 0; i < 8; i++) t += sh[i];
    return t;
}
__device__ __forceinline__ float block_max(float v) {
    __shared__ float sh[8];
    int lane = threadIdx.x & 31, w = threadIdx.x >> 5;
    #pragma unroll
    for (int o = 16; o > 0; o >>= 1) v = fmaxf(v, __shfl_xor_sync(0xffffffffu, v, o));
    __syncthreads();
    if (lane == 0) sh[w] = v;
    __syncthreads();
    float t = -3.4e38f;
    #pragma unroll
    for (int i = 0; i < 8; i++) t = fmaxf(t, sh[i]);
    return t;
}

__global__ void __launch_bounds__(256)
ln_kernel(float* __restrict__ x, const float* __restrict__ gamma,
          const float* __restrict__ beta)
{
    float* p = x + (long)blockIdx.x * D_;
    int t = threadIdx.x;
    float v0 = p[t], v1 = p[t + 256], v2 = p[t + 512];
    float mean = block_sum(v0 + v1 + v2) * (1.0f / D_);
    float d0 = v0 - mean, d1 = v1 - mean, d2 = v2 - mean;
    float var = block_sum(d0 * d0 + d1 * d1 + d2 * d2) * (1.0f / D_);
    float rstd = rsqrtf(var + 1e-5f);
    p[t]       = d0 * rstd * gamma[t]       + beta[t];
    p[t + 256] = d1 * rstd * gamma[t + 256] + beta[t + 256];
    p[t + 512] = d2 * rstd * gamma[t + 512] + beta[t + 512];
}

__global__ void __launch_bounds__(256)
softmax2048_kernel(float* __restrict__ S)
{
    float* p = S + (long)blockIdx.x * LS_;
    int t = threadIdx.x;
    float v[8];
    float m = -3.4e38f;
    #pragma unroll
    for (int i = 0; i < 8; i++) { v[i] = p[t + i * 256]; m = fmaxf(m, v[i]); }
    m = block_max(m);
    float s = 0.f;
    #pragma unroll
    for (int i = 0; i < 8; i++) { v[i] = __expf(v[i] - m); s += v[i]; }
    s = block_sum(s);
    float inv = 1.0f / s;
    #pragma unroll
    for (int i = 0; i < 8; i++) p[t + i * 256] = v[i] * inv;
}

__global__ void __launch_bounds__(256)
softmax768_kernel(const float* __restrict__ O, float* __restrict__ out)
{
    const float* p = O   + (long)blockIdx.x * D_;
    float*       q = out + (long)blockIdx.x * D_;
    int t = threadIdx.x;
    float v0 = p[t], v1 = p[t + 256], v2 = p[t + 512];
    float m = block_max(fmaxf(v0, fmaxf(v1, v2)));
    v0 = __expf(v0 - m); v1 = __expf(v1 - m); v2 = __expf(v2 - m);
    float inv = 1.0f / block_sum(v0 + v1 + v2);
    q[t] = v0 * inv; q[t + 256] = v1 * inv; q[t + 512] = v2 * inv;
}

// ======================= launch ===========================================
extern "C" void kernel_launch(void* const* d_in, const int* in_sizes, int n_in,
                              void* d_out, int out_size)
{
    const float* Q     = (const float*)d_in[0];
    const float* K     = (const float*)d_in[1];
    const float* V     = (const float*)d_in[2];
    const float* Wq    = (const float*)d_in[3];
    const float* Wk    = (const float*)d_in[4];
    const float* Wv    = (const float*)d_in[5];
    const float* gamma = (const float*)d_in[6];
    const float* beta  = (const float*)d_in[7];
    float* out = (float*)d_out;

    float *gq, *gk, *gvT, *gs, *go;
    cudaGetSymbolAddress((void**)&gq,  g_q);
    cudaGetSymbolAddress((void**)&gk,  g_k);
    cudaGetSymbolAddress((void**)&gvT, g_vT);
    cudaGetSymbolAddress((void**)&gs,  g_s);
    cudaGetSymbolAddress((void**)&go,  g_o);

    cudaFuncSetAttribute(tc_gemm<true, 0>,  cudaFuncAttributeMaxDynamicSharedMemorySize, SMEMSZ);
    cudaFuncSetAttribute(tc_gemm<true, 1>,  cudaFuncAttributeMaxDynamicSharedMemorySize, SMEMSZ);
    cudaFuncSetAttribute(tc_gemm<false, 0>, cudaFuncAttributeMaxDynamicSharedMemorySize, SMEMSZ);

    const dim3 blk(256);
    const float scale = 1.0f / sqrtf((float)D_);

    // 1. gather + projections: C[8192,768] = gather(X) @ W^T, K=768
    tc_gemm<true, 0><<<dim3(D_ / BN, MTOT / BM, 1), blk, SMEMSZ>>>(
        Q, Wq, gq, D_, 1.0f, 0, 0, 0, D_, D_, D_);
    tc_gemm<true, 0><<<dim3(D_ / BN, MTOT / BM, 1), blk, SMEMSZ>>>(
        K, Wk, gk, D_, 1.0f, 0, 0, 0, D_, D_, D_);
    tc_gemm<true, 1><<<dim3(D_ / BN, MTOT / BM, 1), blk, SMEMSZ>>>(
        V, Wv, gvT, D_, 1.0f, 0, 0, 0, D_, D_, 0);

    // 2. qk LayerNorm
    ln_kernel<<<MTOT, blk>>>(gq, gamma, beta);
    ln_kernel<<<MTOT, blk>>>(gk, gamma, beta);

    // 3. S = q k^T * scale (per batch, both K-major)
    tc_gemm<false, 0><<<dim3(LS_ / BN, LS_ / BM, B_), blk, SMEMSZ>>>(
        gq, gk, gs, D_, scale,
        (long)LS_ * D_, (long)LS_ * D_, (long)LS_ * LS_, D_, D_, LS_);

    // 4. row softmax
    softmax2048_kernel<<<B_ * LS_, blk>>>(gs);

    // 5. O = P v   (B = vT, rows of length 2048, K=2048)
    tc_gemm<false, 0><<<dim3(D_ / BN, LS_ / BM, B_), blk, SMEMSZ>>>(
        gs, gvT, go, LS_, 1.0f,
        (long)LS_ * LS_, (long)D_ * LS_, (long)LS_ * D_, LS_, LS_, D_);

    // 6. feature softmax -> out
    softmax768_kernel<<<MTOT, blk>>>(go, out);
}